// round 8
// baseline (speedup 1.0000x reference)
#include <cuda_runtime.h>

#define SEQ 4096
#define HID 1024
#define NCTA 32
#define EPSF 1e-12f

// Scratch (allocation-free rule: __device__ globals)
__device__ float g_Xn[SEQ * HID];      // normalized embeddings
__device__ float g_P[SEQ * HID];       // W_hi @ x_t + b, precomputed
__device__ float g_Hf[2][HID];         // h double buffer (plain floats)
__device__ unsigned g_cnt[8];          // striped cumulative arrival counters

// ---------------- primitives ----------------
__device__ __forceinline__ void st_cg_f2(float* p, float a, float b) {
    asm volatile("st.global.cg.v2.f32 [%0], {%1,%2};" :: "l"(p), "f"(a), "f"(b) : "memory");
}
__device__ __forceinline__ float2 ld_cg_f2(const float* p) {
    float a, b;
    asm volatile("ld.global.cg.v2.f32 {%0,%1}, [%2];" : "=f"(a), "=f"(b) : "l"(p) : "memory");
    return make_float2(a, b);
}
__device__ __forceinline__ unsigned ld_acq(const unsigned* p) {
    unsigned v;
    asm volatile("ld.acquire.gpu.global.u32 %0, [%1];" : "=r"(v) : "l"(p) : "memory");
    return v;
}
__device__ __forceinline__ void red_add_rel(unsigned* p) {
    asm volatile("red.add.release.gpu.global.u32 [%0], 1;" :: "l"(p) : "memory");
}

// ---------------- fast tanh: 1 - 2/(e^{2x}+1) via ex2/rcp approx ----------------
__device__ __forceinline__ float fast_tanh(float x) {
    float e;
    asm("ex2.approx.f32 %0, %1;" : "=f"(e) : "f"(x * 2.8853900817779268f)); // 2*log2(e)
    float r;
    asm("rcp.approx.f32 %0, %1;" : "=f"(r) : "f"(e + 1.0f));
    return fmaf(-2.0f, r, 1.0f);
}

// ---------------- init: h0 -> out[0] + buf[0]; counters = 64 (h0 epoch) ----------------
__global__ __launch_bounds__(1024) void init_kernel(const float* __restrict__ h0,
                                                    float* __restrict__ out) {
    int i = threadIdx.x;
    float v = h0[i];
    out[i] = v;
    g_Hf[0][i] = v;
    if (i < 8) g_cnt[i] = 64;   // 512/8 warps "published" h_0
}

// ---------------- embedding + L2 normalize ----------------
__global__ __launch_bounds__(256) void embed_kernel(const int* __restrict__ src,
                                                    const float* __restrict__ W) {
    const int t   = blockIdx.x;
    const int tid = threadIdx.x;
    const float4* row = reinterpret_cast<const float4*>(W) + (size_t)src[t] * (HID / 4);
    float4 v = row[tid];
    float s = v.x * v.x + v.y * v.y + v.z * v.z + v.w * v.w;
    #pragma unroll
    for (int o = 16; o; o >>= 1) s += __shfl_xor_sync(0xffffffffu, s, o);
    __shared__ float red[8];
    if ((tid & 31) == 0) red[tid >> 5] = s;
    __syncthreads();
    float tot = red[0] + red[1] + red[2] + red[3] + red[4] + red[5] + red[6] + red[7];
    float rn = 1.0f / fmaxf(sqrtf(tot), EPSF);
    float4 o4 = make_float4(v.x * rn, v.y * rn, v.z * rn, v.w * rn);
    reinterpret_cast<float4*>(g_Xn)[(size_t)t * (HID / 4) + tid] = o4;
}

// ---------------- GEMM: g_P[m][n] = sum_k g_Xn[m][k] * W_hi[n][k] + b[n] ----------------
#define BM 128
#define BN 64
#define BK 32
__global__ __launch_bounds__(256) void gemm_kernel(const float* __restrict__ Bw,
                                                   const float* __restrict__ bias) {
    __shared__ float As[BK][BM + 4];
    __shared__ float Bs[BK][BN + 4];
    const int tid = threadIdx.x;
    const int m0 = blockIdx.y * BM;
    const int n0 = blockIdx.x * BN;
    const int ty = tid >> 4;
    const int tx = tid & 15;

    float acc[8][4];
    #pragma unroll
    for (int i = 0; i < 8; i++)
        #pragma unroll
        for (int j = 0; j < 4; j++) acc[i][j] = 0.0f;

    for (int k0 = 0; k0 < HID; k0 += BK) {
        #pragma unroll
        for (int i = 0; i < 4; i++) {
            int idx = tid + i * 256;
            int r = idx >> 3;
            int kq = idx & 7;
            float4 f = reinterpret_cast<const float4*>(g_Xn)[(size_t)(m0 + r) * (HID / 4) + (k0 >> 2) + kq];
            As[kq * 4 + 0][r] = f.x;
            As[kq * 4 + 1][r] = f.y;
            As[kq * 4 + 2][r] = f.z;
            As[kq * 4 + 3][r] = f.w;
        }
        #pragma unroll
        for (int i = 0; i < 2; i++) {
            int idx = tid + i * 256;
            int r = idx >> 3;
            int kq = idx & 7;
            float4 f = reinterpret_cast<const float4*>(Bw)[(size_t)(n0 + r) * (HID / 4) + (k0 >> 2) + kq];
            Bs[kq * 4 + 0][r] = f.x;
            Bs[kq * 4 + 1][r] = f.y;
            Bs[kq * 4 + 2][r] = f.z;
            Bs[kq * 4 + 3][r] = f.w;
        }
        __syncthreads();
        #pragma unroll
        for (int k = 0; k < BK; k++) {
            float4 a0 = *reinterpret_cast<const float4*>(&As[k][ty * 8]);
            float4 a1 = *reinterpret_cast<const float4*>(&As[k][ty * 8 + 4]);
            float4 b0 = *reinterpret_cast<const float4*>(&Bs[k][tx * 4]);
            float ar[8] = {a0.x, a0.y, a0.z, a0.w, a1.x, a1.y, a1.z, a1.w};
            float br[4] = {b0.x, b0.y, b0.z, b0.w};
            #pragma unroll
            for (int i = 0; i < 8; i++)
                #pragma unroll
                for (int j = 0; j < 4; j++)
                    acc[i][j] = fmaf(ar[i], br[j], acc[i][j]);
        }
        __syncthreads();
    }

    float4 bb = reinterpret_cast<const float4*>(bias)[(n0 >> 2) + tx];
    #pragma unroll
    for (int i = 0; i < 8; i++) {
        int m = m0 + ty * 8 + i;
        float4 o = make_float4(acc[i][0] + bb.x, acc[i][1] + bb.y,
                               acc[i][2] + bb.z, acc[i][3] + bb.w);
        reinterpret_cast<float4*>(g_P)[(size_t)m * (HID / 4) + (n0 >> 2) + tx] = o;
    }
}

// ---------------- persistent RNN: epoch counters + one-shot bulk read ----------------
// 32 CTAs x 16 warps (512 thr). Warp w of CTA c owns rows c*32+2w, c*32+2w+1.
// Publish: lane0 st.cg (plain float2) then red.add.release into striped counter.
// Detect: thread 0 of each CTA acquire-polls 8 counters (>= 64*step); everyone
// else sleeps at __syncthreads. Then 512 threads bulk-read h ONCE (8B each),
// stage into parity-double smem, bar, compute. Detection traffic ~= zero.
__global__ __launch_bounds__(512) void rnn_kernel(const float* __restrict__ Whh,
                                                  float* __restrict__ out) {
    __shared__ float shf[2][HID];                // 8 KB staging
    const int tid  = threadIdx.x;
    const int warp = tid >> 5;
    const int lane = tid & 31;
    const int rowA = (blockIdx.x << 5) + (warp << 1);
    const int rowB = rowA + 1;

    // weights for both rows in registers (16 float4 = 64 regs)
    float4 wa[8], wb[8];
    {
        const float4* wra = reinterpret_cast<const float4*>(Whh) + (size_t)rowA * (HID / 4);
        const float4* wrb = wra + (HID / 4);
        #pragma unroll
        for (int j = 0; j < 8; j++) { wa[j] = wra[lane + (j << 5)]; wb[j] = wrb[lane + (j << 5)]; }
    }

    float pa = g_P[rowA], pb = g_P[rowB];

    for (int t = 0; t < SEQ; ++t) {
        const int par = t & 1;
        const unsigned target = (unsigned)(64 * (t + 1));   // h_t fully published

        // prefetch next-step P (independent of h)
        float pan = 0.f, pbn = 0.f;
        if (t + 1 < SEQ) {
            pan = g_P[(size_t)(t + 1) * HID + rowA];
            pbn = g_P[(size_t)(t + 1) * HID + rowB];
        }

        // 1) detect: single poller per CTA on the striped counters
        if (tid == 0) {
            for (;;) {
                unsigned m = 0xffffffffu;
                #pragma unroll
                for (int k = 0; k < 8; k++) {
                    unsigned c = ld_acq(&g_cnt[k]);
                    m &= (unsigned)-(int)(c >= target);
                }
                if (m) break;
            }
        }
        __syncthreads();

        // 2) one-shot bulk read of h_t (8B per thread), stage to smem
        {
            float2 hv = ld_cg_f2(&g_Hf[par][tid << 1]);
            reinterpret_cast<float2*>(shf[par])[tid] = hv;
        }
        __syncthreads();

        // 3) dual-row dot product from smem (8 conflict-free LDS.128)
        const float4* hv4 = reinterpret_cast<const float4*>(shf[par]);
        float a0 = 0.f, a1 = 0.f, b0 = 0.f, b1 = 0.f;
        #pragma unroll
        for (int j = 0; j < 8; j++) {
            float4 h = hv4[lane + (j << 5)];
            a0 = fmaf(wa[j].x, h.x, a0); a1 = fmaf(wa[j].y, h.y, a1);
            a0 = fmaf(wa[j].z, h.z, a0); a1 = fmaf(wa[j].w, h.w, a1);
            b0 = fmaf(wb[j].x, h.x, b0); b1 = fmaf(wb[j].y, h.y, b1);
            b0 = fmaf(wb[j].z, h.z, b0); b1 = fmaf(wb[j].w, h.w, b1);
        }
        float sa = a0 + a1, sb = b0 + b1;
        #pragma unroll
        for (int o = 16; o; o >>= 1) {
            sa += __shfl_xor_sync(0xffffffffu, sa, o);
            sb += __shfl_xor_sync(0xffffffffu, sb, o);
        }

        // 4) lane 0: tanh x2, publish data, then release-increment striped counter
        if (lane == 0) {
            float hA = fast_tanh(sa + pa);
            float hB = fast_tanh(sb + pb);
            st_cg_f2(&g_Hf[(t + 1) & 1][rowA], hA, hB);
            reinterpret_cast<float2*>(out + (size_t)(t + 1) * HID)[rowA >> 1] =
                make_float2(hA, hB);
            red_add_rel(&g_cnt[warp & 7]);
        }
        pa = pan; pb = pbn;
    }
}

// ---------------- launch ----------------
extern "C" void kernel_launch(void* const* d_in, const int* in_sizes, int n_in,
                              void* d_out, int out_size) {
    const int*   src  = (const int*)  d_in[0];  // [4096]
    const float* W    = (const float*)d_in[1];  // [32000,1024]
    const float* h0   = (const float*)d_in[2];  // [1024]
    const float* W_hi = (const float*)d_in[3];  // [1024,1024]
    const float* W_hh = (const float*)d_in[4];  // [1024,1024]
    const float* b    = (const float*)d_in[5];  // [1024]
    float* out = (float*)d_out;                 // [4097,1024]

    init_kernel<<<1, 1024>>>(h0, out);
    embed_kernel<<<SEQ, 256>>>(src, W);
    gemm_kernel<<<dim3(HID / BN, SEQ / BM), 256>>>(W_hi, b);
    rnn_kernel<<<NCTA, 512>>>(W_hh, out);
}

// round 9
// speedup vs baseline: 1.9760x; 1.9760x over previous
#include <cuda_runtime.h>

#define SEQ 4096
#define HID 1024
#define NCTA 32
#define EPSF 1e-12f

// Scratch (allocation-free rule: __device__ globals)
__device__ float g_Xn[SEQ * HID];              // normalized embeddings
__device__ float g_P[SEQ * HID];               // W_hi @ x_t + b, precomputed
__device__ unsigned long long g_H[2 * HID];    // tagged h double buffer: hi32=tag, lo32=float bits

// ---------------- weak L2-cached ld/st (fast path) ----------------
__device__ __forceinline__ unsigned long long ld_cg(const unsigned long long* p) {
    unsigned long long v;
    asm volatile("ld.global.cg.u64 %0, [%1];" : "=l"(v) : "l"(p) : "memory");
    return v;
}
__device__ __forceinline__ void ld_cg_v2(const unsigned long long* p,
                                         unsigned long long& a, unsigned long long& b) {
    asm volatile("ld.global.cg.v2.u64 {%0,%1}, [%2];" : "=l"(a), "=l"(b) : "l"(p) : "memory");
}
__device__ __forceinline__ void st_cg_v2(unsigned long long* p,
                                         unsigned long long a, unsigned long long b) {
    asm volatile("st.global.cg.v2.u64 [%0], {%1,%2};" :: "l"(p), "l"(a), "l"(b) : "memory");
}
// ---------------- strong relaxed load (progress-guarantee fallback only) ----------------
__device__ __forceinline__ unsigned long long ld_rlx(const unsigned long long* p) {
    unsigned long long v;
    asm volatile("ld.relaxed.gpu.global.u64 %0, [%1];" : "=l"(v) : "l"(p) : "memory");
    return v;
}

// ---------------- f32x2 packed helpers ----------------
__device__ __forceinline__ unsigned long long packff(float a, float b) {
    unsigned long long r;
    asm("mov.b64 %0, {%1,%2};" : "=l"(r) : "r"(__float_as_uint(a)), "r"(__float_as_uint(b)));
    return r;
}
__device__ __forceinline__ void fma2(unsigned long long& acc, unsigned long long w,
                                     unsigned long long h) {
    asm("fma.rn.f32x2 %0, %1, %2, %0;" : "+l"(acc) : "l"(w), "l"(h));
}
__device__ __forceinline__ float sum2(unsigned long long a, unsigned long long b) {
    unsigned long long s;
    asm("add.rn.f32x2 %0, %1, %2;" : "=l"(s) : "l"(a), "l"(b));
    unsigned lo, hi;
    asm("mov.b64 {%0,%1}, %2;" : "=r"(lo), "=r"(hi) : "l"(s));
    return __uint_as_float(lo) + __uint_as_float(hi);
}

// ---------------- fast tanh: 1 - 2/(e^{2x}+1) via ex2/rcp approx ----------------
__device__ __forceinline__ float fast_tanh(float x) {
    float e;
    asm("ex2.approx.f32 %0, %1;" : "=f"(e) : "f"(x * 2.8853900817779268f)); // 2*log2(e)
    float r;
    asm("rcp.approx.f32 %0, %1;" : "=f"(r) : "f"(e + 1.0f));
    return fmaf(-2.0f, r, 1.0f);
}

// ---------------- init: h0 -> out[0], tagged buf[0] (tag 1), clear buf[1] ----------------
__global__ __launch_bounds__(1024) void init_kernel(const float* __restrict__ h0,
                                                    float* __restrict__ out) {
    int i = threadIdx.x;
    float v = h0[i];
    out[i] = v;
    g_H[i]       = (1ull << 32) | (unsigned long long)__float_as_uint(v);
    g_H[HID + i] = 0ull;
}

// ---------------- embedding + L2 normalize ----------------
__global__ __launch_bounds__(256) void embed_kernel(const int* __restrict__ src,
                                                    const float* __restrict__ W) {
    const int t   = blockIdx.x;
    const int tid = threadIdx.x;
    const float4* row = reinterpret_cast<const float4*>(W) + (size_t)src[t] * (HID / 4);
    float4 v = row[tid];
    float s = v.x * v.x + v.y * v.y + v.z * v.z + v.w * v.w;
    #pragma unroll
    for (int o = 16; o; o >>= 1) s += __shfl_xor_sync(0xffffffffu, s, o);
    __shared__ float red[8];
    if ((tid & 31) == 0) red[tid >> 5] = s;
    __syncthreads();
    float tot = red[0] + red[1] + red[2] + red[3] + red[4] + red[5] + red[6] + red[7];
    float rn = 1.0f / fmaxf(sqrtf(tot), EPSF);
    float4 o4 = make_float4(v.x * rn, v.y * rn, v.z * rn, v.w * rn);
    reinterpret_cast<float4*>(g_Xn)[(size_t)t * (HID / 4) + tid] = o4;
}

// ---------------- GEMM: g_P[m][n] = sum_k g_Xn[m][k] * W_hi[n][k] + b[n] ----------------
#define BM 128
#define BN 64
#define BK 32
__global__ __launch_bounds__(256) void gemm_kernel(const float* __restrict__ Bw,
                                                   const float* __restrict__ bias) {
    __shared__ float As[BK][BM + 4];
    __shared__ float Bs[BK][BN + 4];
    const int tid = threadIdx.x;
    const int m0 = blockIdx.y * BM;
    const int n0 = blockIdx.x * BN;
    const int ty = tid >> 4;
    const int tx = tid & 15;

    float acc[8][4];
    #pragma unroll
    for (int i = 0; i < 8; i++)
        #pragma unroll
        for (int j = 0; j < 4; j++) acc[i][j] = 0.0f;

    for (int k0 = 0; k0 < HID; k0 += BK) {
        #pragma unroll
        for (int i = 0; i < 4; i++) {
            int idx = tid + i * 256;
            int r = idx >> 3;
            int kq = idx & 7;
            float4 f = reinterpret_cast<const float4*>(g_Xn)[(size_t)(m0 + r) * (HID / 4) + (k0 >> 2) + kq];
            As[kq * 4 + 0][r] = f.x;
            As[kq * 4 + 1][r] = f.y;
            As[kq * 4 + 2][r] = f.z;
            As[kq * 4 + 3][r] = f.w;
        }
        #pragma unroll
        for (int i = 0; i < 2; i++) {
            int idx = tid + i * 256;
            int r = idx >> 3;
            int kq = idx & 7;
            float4 f = reinterpret_cast<const float4*>(Bw)[(size_t)(n0 + r) * (HID / 4) + (k0 >> 2) + kq];
            Bs[kq * 4 + 0][r] = f.x;
            Bs[kq * 4 + 1][r] = f.y;
            Bs[kq * 4 + 2][r] = f.z;
            Bs[kq * 4 + 3][r] = f.w;
        }
        __syncthreads();
        #pragma unroll
        for (int k = 0; k < BK; k++) {
            float4 a0 = *reinterpret_cast<const float4*>(&As[k][ty * 8]);
            float4 a1 = *reinterpret_cast<const float4*>(&As[k][ty * 8 + 4]);
            float4 b0 = *reinterpret_cast<const float4*>(&Bs[k][tx * 4]);
            float ar[8] = {a0.x, a0.y, a0.z, a0.w, a1.x, a1.y, a1.z, a1.w};
            float br[4] = {b0.x, b0.y, b0.z, b0.w};
            #pragma unroll
            for (int i = 0; i < 8; i++)
                #pragma unroll
                for (int j = 0; j < 4; j++)
                    acc[i][j] = fmaf(ar[i], br[j], acc[i][j]);
        }
        __syncthreads();
    }

    float4 bb = reinterpret_cast<const float4*>(bias)[(n0 >> 2) + tx];
    #pragma unroll
    for (int i = 0; i < 8; i++) {
        int m = m0 + ty * 8 + i;
        float4 o = make_float4(acc[i][0] + bb.x, acc[i][1] + bb.y,
                               acc[i][2] + bb.z, acc[i][3] + bb.w);
        reinterpret_cast<float4*>(g_P)[(size_t)m * (HID / 4) + (n0 >> 2) + tx] = o;
    }
}

// ---------------- persistent RNN: tagged dataflow + straggler-only polling ----------------
// 32 CTAs x 16 warps (512 thr). Warp w of CTA c owns rows c*32+2w, c*32+2w+1,
// and stages global tagged chunk [w*64, (w+1)*64) into plain-float smem.
// Sync: value+step-tag in one weak .cg u64 (atomic 8B => value/flag coherent,
// no cross-address ordering needed). Poll loop only reloads slots whose tag
// hasn't matched yet (kills the re-read storm). Strong relaxed fallback every
// 64 spins = formal progress guarantee. One __syncthreads per step; parity
// double-buffered smem; distance-2 overwrite induction unchanged.
__global__ __launch_bounds__(512) void rnn_kernel(const float* __restrict__ Whh,
                                                  float* __restrict__ out) {
    __shared__ float shf[2][HID];                // 8 KB: [parity][h]
    const int warp = threadIdx.x >> 5;
    const int lane = threadIdx.x & 31;
    const int rowA = (blockIdx.x << 5) + (warp << 1);
    const int rowB = rowA + 1;

    // weights for both rows as packed f32x2 (16 u64 per row = 64 regs total)
    unsigned long long wA[16], wB[16];
    {
        const float4* wra = reinterpret_cast<const float4*>(Whh) + (size_t)rowA * (HID / 4);
        const float4* wrb = wra + (HID / 4);
        #pragma unroll
        for (int k = 0; k < 8; k++) {
            float4 a = wra[lane + (k << 5)];
            float4 b = wrb[lane + (k << 5)];
            wA[2 * k] = packff(a.x, a.y); wA[2 * k + 1] = packff(a.z, a.w);
            wB[2 * k] = packff(b.x, b.y); wB[2 * k + 1] = packff(b.z, b.w);
        }
    }

    float pa = g_P[rowA], pb = g_P[rowB];
    const int slot = (warp << 6) + (lane << 1);    // 2 u64 slots per lane

    for (int t = 0; t < SEQ; ++t) {
        const unsigned tag = (unsigned)(t + 1);    // tag of h_t
        const int par = t & 1;

        // prefetch next-step P (independent of h)
        float pan = 0.f, pbn = 0.f;
        if (t + 1 < SEQ) {
            pan = g_P[(size_t)(t + 1) * HID + rowA];
            pbn = g_P[(size_t)(t + 1) * HID + rowB];
        }

        // 1) poll my 2 tagged slots; reload ONLY slots still pending
        unsigned long long v0, v1;
        {
            const unsigned long long* gp = g_H + (par << 10) + slot;
            ld_cg_v2(gp, v0, v1);
            bool d0 = ((unsigned)(v0 >> 32) == tag);
            bool d1 = ((unsigned)(v1 >> 32) == tag);
            int spins = 0;
            while (!(d0 && d1)) {
                if ((++spins & 63) == 0) {         // rare strong fallback (progress)
                    if (!d0) { v0 = ld_rlx(gp);     d0 = ((unsigned)(v0 >> 32) == tag); }
                    if (!d1) { v1 = ld_rlx(gp + 1); d1 = ((unsigned)(v1 >> 32) == tag); }
                } else {
                    if (!d0) { v0 = ld_cg(gp);      d0 = ((unsigned)(v0 >> 32) == tag); }
                    if (!d1) { v1 = ld_cg(gp + 1);  d1 = ((unsigned)(v1 >> 32) == tag); }
                }
            }
        }

        // 2) stage plain floats to smem, then one CTA barrier
        reinterpret_cast<float2*>(shf[par])[slot >> 1] =
            make_float2(__uint_as_float((unsigned)v0), __uint_as_float((unsigned)v1));
        __syncthreads();

        // 3) dual-row dot product, packed f32x2 (8x LDS v2.u64 + 32 FFMA2)
        const unsigned shb = (unsigned)__cvta_generic_to_shared(&shf[par][0]);
        unsigned long long aA0 = 0ull, aA1 = 0ull, aB0 = 0ull, aB1 = 0ull;
        #pragma unroll
        for (int k = 0; k < 8; k++) {
            unsigned long long h01, h23;
            unsigned ad = shb + ((unsigned)(lane + (k << 5)) << 4);   // float4-aligned
            asm volatile("ld.shared.v2.u64 {%0,%1}, [%2];"
                         : "=l"(h01), "=l"(h23) : "r"(ad));
            fma2(aA0, wA[2 * k], h01); fma2(aA1, wA[2 * k + 1], h23);
            fma2(aB0, wB[2 * k], h01); fma2(aB1, wB[2 * k + 1], h23);
        }
        float sa = sum2(aA0, aA1);
        float sb = sum2(aB0, aB1);
        #pragma unroll
        for (int o = 16; o; o >>= 1) {
            sa += __shfl_xor_sync(0xffffffffu, sa, o);
            sb += __shfl_xor_sync(0xffffffffu, sb, o);
        }

        // 4) lane 0: both tanhs, one 16B tagged publish + one 8B out store
        if (lane == 0) {
            float hA = fast_tanh(sa + pa);
            float hB = fast_tanh(sb + pb);
            unsigned long long tg = (unsigned long long)(unsigned)(t + 2) << 32;
            st_cg_v2(g_H + (((t + 1) & 1) << 10) + rowA,
                     tg | (unsigned long long)__float_as_uint(hA),
                     tg | (unsigned long long)__float_as_uint(hB));
            reinterpret_cast<float2*>(out + (size_t)(t + 1) * HID)[rowA >> 1] =
                make_float2(hA, hB);
        }
        pa = pan; pb = pbn;
    }
}

// ---------------- launch ----------------
extern "C" void kernel_launch(void* const* d_in, const int* in_sizes, int n_in,
                              void* d_out, int out_size) {
    const int*   src  = (const int*)  d_in[0];  // [4096]
    const float* W    = (const float*)d_in[1];  // [32000,1024]
    const float* h0   = (const float*)d_in[2];  // [1024]
    const float* W_hi = (const float*)d_in[3];  // [1024,1024]
    const float* W_hh = (const float*)d_in[4];  // [1024,1024]
    const float* b    = (const float*)d_in[5];  // [1024]
    float* out = (float*)d_out;                 // [4097,1024]

    init_kernel<<<1, 1024>>>(h0, out);
    embed_kernel<<<SEQ, 256>>>(src, W);
    gemm_kernel<<<dim3(HID / BN, SEQ / BM), 256>>>(W_hi, b);
    rnn_kernel<<<NCTA, 512>>>(W_hh, out);
}

// round 10
// speedup vs baseline: 2.5793x; 1.3053x over previous
#include <cuda_runtime.h>

#define SEQ 4096
#define HID 1024
#define NCTA 32
#define EPSF 1e-12f

// Scratch (allocation-free rule: __device__ globals)
__device__ float g_Xn[SEQ * HID];              // normalized embeddings
__device__ float g_P[SEQ * HID];               // W_hi @ x_t + b, precomputed
__device__ unsigned long long g_H[2 * HID];    // tagged h double buffer: hi32=tag, lo32=float bits

// ---------------- weak L2-cached ld/st (fast path) ----------------
__device__ __forceinline__ void ld_cg_v2(const unsigned long long* p,
                                         unsigned long long& a, unsigned long long& b) {
    asm volatile("ld.global.cg.v2.u64 {%0,%1}, [%2];" : "=l"(a), "=l"(b) : "l"(p) : "memory");
}
__device__ __forceinline__ void st_cg_v2(unsigned long long* p,
                                         unsigned long long a, unsigned long long b) {
    asm volatile("st.global.cg.v2.u64 [%0], {%1,%2};" :: "l"(p), "l"(a), "l"(b) : "memory");
}
// ---------------- strong relaxed load (progress-guarantee fallback only) ----------------
__device__ __forceinline__ unsigned long long ld_rlx(const unsigned long long* p) {
    unsigned long long v;
    asm volatile("ld.relaxed.gpu.global.u64 %0, [%1];" : "=l"(v) : "l"(p) : "memory");
    return v;
}

// ---------------- f32x2 packed helpers ----------------
__device__ __forceinline__ unsigned long long packff(float a, float b) {
    unsigned long long r;
    asm("mov.b64 %0, {%1,%2};" : "=l"(r) : "r"(__float_as_uint(a)), "r"(__float_as_uint(b)));
    return r;
}
__device__ __forceinline__ void fma2(unsigned long long& acc, unsigned long long w,
                                     unsigned long long h) {
    asm("fma.rn.f32x2 %0, %1, %2, %0;" : "+l"(acc) : "l"(w), "l"(h));
}
__device__ __forceinline__ float sum2(unsigned long long a, unsigned long long b) {
    unsigned long long s;
    asm("add.rn.f32x2 %0, %1, %2;" : "=l"(s) : "l"(a), "l"(b));
    unsigned lo, hi;
    asm("mov.b64 {%0,%1}, %2;" : "=r"(lo), "=r"(hi) : "l"(s));
    return __uint_as_float(lo) + __uint_as_float(hi);
}

// ---------------- fast tanh: 1 - 2/(e^{2x}+1) via ex2/rcp approx ----------------
__device__ __forceinline__ float fast_tanh(float x) {
    float e;
    asm("ex2.approx.f32 %0, %1;" : "=f"(e) : "f"(x * 2.8853900817779268f)); // 2*log2(e)
    float r;
    asm("rcp.approx.f32 %0, %1;" : "=f"(r) : "f"(e + 1.0f));
    return fmaf(-2.0f, r, 1.0f);
}

// ---------------- init: h0 -> out[0], tagged buf[0] (tag 1), clear buf[1] ----------------
__global__ __launch_bounds__(1024) void init_kernel(const float* __restrict__ h0,
                                                    float* __restrict__ out) {
    int i = threadIdx.x;
    float v = h0[i];
    out[i] = v;
    g_H[i]       = (1ull << 32) | (unsigned long long)__float_as_uint(v);
    g_H[HID + i] = 0ull;
}

// ---------------- embedding + L2 normalize ----------------
__global__ __launch_bounds__(256) void embed_kernel(const int* __restrict__ src,
                                                    const float* __restrict__ W) {
    const int t   = blockIdx.x;
    const int tid = threadIdx.x;
    const float4* row = reinterpret_cast<const float4*>(W) + (size_t)src[t] * (HID / 4);
    float4 v = row[tid];
    float s = v.x * v.x + v.y * v.y + v.z * v.z + v.w * v.w;
    #pragma unroll
    for (int o = 16; o; o >>= 1) s += __shfl_xor_sync(0xffffffffu, s, o);
    __shared__ float red[8];
    if ((tid & 31) == 0) red[tid >> 5] = s;
    __syncthreads();
    float tot = red[0] + red[1] + red[2] + red[3] + red[4] + red[5] + red[6] + red[7];
    float rn = 1.0f / fmaxf(sqrtf(tot), EPSF);
    float4 o4 = make_float4(v.x * rn, v.y * rn, v.z * rn, v.w * rn);
    reinterpret_cast<float4*>(g_Xn)[(size_t)t * (HID / 4) + tid] = o4;
}

// ---------------- GEMM: g_P[m][n] = sum_k g_Xn[m][k] * W_hi[n][k] + b[n] ----------------
#define BM 128
#define BN 64
#define BK 32
__global__ __launch_bounds__(256) void gemm_kernel(const float* __restrict__ Bw,
                                                   const float* __restrict__ bias) {
    __shared__ float As[BK][BM + 4];
    __shared__ float Bs[BK][BN + 4];
    const int tid = threadIdx.x;
    const int m0 = blockIdx.y * BM;
    const int n0 = blockIdx.x * BN;
    const int ty = tid >> 4;
    const int tx = tid & 15;

    float acc[8][4];
    #pragma unroll
    for (int i = 0; i < 8; i++)
        #pragma unroll
        for (int j = 0; j < 4; j++) acc[i][j] = 0.0f;

    for (int k0 = 0; k0 < HID; k0 += BK) {
        #pragma unroll
        for (int i = 0; i < 4; i++) {
            int idx = tid + i * 256;
            int r = idx >> 3;
            int kq = idx & 7;
            float4 f = reinterpret_cast<const float4*>(g_Xn)[(size_t)(m0 + r) * (HID / 4) + (k0 >> 2) + kq];
            As[kq * 4 + 0][r] = f.x;
            As[kq * 4 + 1][r] = f.y;
            As[kq * 4 + 2][r] = f.z;
            As[kq * 4 + 3][r] = f.w;
        }
        #pragma unroll
        for (int i = 0; i < 2; i++) {
            int idx = tid + i * 256;
            int r = idx >> 3;
            int kq = idx & 7;
            float4 f = reinterpret_cast<const float4*>(Bw)[(size_t)(n0 + r) * (HID / 4) + (k0 >> 2) + kq];
            Bs[kq * 4 + 0][r] = f.x;
            Bs[kq * 4 + 1][r] = f.y;
            Bs[kq * 4 + 2][r] = f.z;
            Bs[kq * 4 + 3][r] = f.w;
        }
        __syncthreads();
        #pragma unroll
        for (int k = 0; k < BK; k++) {
            float4 a0 = *reinterpret_cast<const float4*>(&As[k][ty * 8]);
            float4 a1 = *reinterpret_cast<const float4*>(&As[k][ty * 8 + 4]);
            float4 b0 = *reinterpret_cast<const float4*>(&Bs[k][tx * 4]);
            float ar[8] = {a0.x, a0.y, a0.z, a0.w, a1.x, a1.y, a1.z, a1.w};
            float br[4] = {b0.x, b0.y, b0.z, b0.w};
            #pragma unroll
            for (int i = 0; i < 8; i++)
                #pragma unroll
                for (int j = 0; j < 4; j++)
                    acc[i][j] = fmaf(ar[i], br[j], acc[i][j]);
        }
        __syncthreads();
    }

    float4 bb = reinterpret_cast<const float4*>(bias)[(n0 >> 2) + tx];
    #pragma unroll
    for (int i = 0; i < 8; i++) {
        int m = m0 + ty * 8 + i;
        float4 o = make_float4(acc[i][0] + bb.x, acc[i][1] + bb.y,
                               acc[i][2] + bb.z, acc[i][3] + bb.w);
        reinterpret_cast<float4*>(g_P)[(size_t)m * (HID / 4) + (n0 >> 2) + tx] = o;
    }
}

// ---------------- persistent RNN: tagged dataflow (R6 poll + R7 topo + R9 math) ----------------
// 32 CTAs x 16 warps (512 thr). Warp w of CTA c owns rows c*32+2w, c*32+2w+1,
// and stages global tagged chunk [w*64, (w+1)*64) into plain-float smem
// (one 16B v2.u64 poll slot per lane). Sync: value+step-tag in one weak .cg
// u64 (8B-atomic => value/flag coherent, no cross-address ordering needed);
// uniform non-divergent v2 re-poll, NO pacing; strong relaxed fallback every
// 64 spins = formal progress guarantee. One __syncthreads per step; parity
// double-buffered smem; distance-2 overwrite induction unchanged.
__global__ __launch_bounds__(512) void rnn_kernel(const float* __restrict__ Whh,
                                                  float* __restrict__ out) {
    __shared__ float4 shf[2][HID / 4];           // 8 KB, 16B-aligned staging
    const int warp = threadIdx.x >> 5;
    const int lane = threadIdx.x & 31;
    const int rowA = (blockIdx.x << 5) + (warp << 1);
    const int rowB = rowA + 1;

    // weights for both rows as packed f32x2 (16 u64 per row = 64 regs total)
    unsigned long long wA[16], wB[16];
    {
        const float4* wra = reinterpret_cast<const float4*>(Whh) + (size_t)rowA * (HID / 4);
        const float4* wrb = wra + (HID / 4);
        #pragma unroll
        for (int k = 0; k < 8; k++) {
            float4 a = wra[lane + (k << 5)];
            float4 b = wrb[lane + (k << 5)];
            wA[2 * k] = packff(a.x, a.y); wA[2 * k + 1] = packff(a.z, a.w);
            wB[2 * k] = packff(b.x, b.y); wB[2 * k + 1] = packff(b.z, b.w);
        }
    }

    float pa = g_P[rowA], pb = g_P[rowB];
    const int slot = (warp << 6) + (lane << 1);    // 2 u64 slots per lane

    for (int t = 0; t < SEQ; ++t) {
        const unsigned tag = (unsigned)(t + 1);    // tag of h_t
        const int par = t & 1;

        // prefetch next-step P (independent of h)
        float pan = 0.f, pbn = 0.f;
        if (t + 1 < SEQ) {
            pan = g_P[(size_t)(t + 1) * HID + rowA];
            pbn = g_P[(size_t)(t + 1) * HID + rowB];
        }

        // 1) poll my 2 tagged slots: uniform 16B .cg re-poll, no pacing
        unsigned long long v0, v1;
        {
            const unsigned long long* gp = g_H + (par << 10) + slot;
            int spins = 0;
            for (;;) {
                ld_cg_v2(gp, v0, v1);
                if ((((unsigned)(v0 >> 32) == tag) & ((unsigned)(v1 >> 32) == tag))) break;
                if ((++spins & 63) == 0) {         // rare strong fallback (progress)
                    v0 = ld_rlx(gp); v1 = ld_rlx(gp + 1);
                    if ((((unsigned)(v0 >> 32) == tag) & ((unsigned)(v1 >> 32) == tag))) break;
                }
            }
        }

        // 2) stage plain floats to smem, then one CTA barrier
        reinterpret_cast<float2*>(&shf[par][0])[slot >> 1] =
            make_float2(__uint_as_float((unsigned)v0), __uint_as_float((unsigned)v1));
        __syncthreads();

        // 3) dual-row dot product, packed f32x2 (8x LDS v2.u64 + 32 FFMA2)
        const unsigned shb = (unsigned)__cvta_generic_to_shared(&shf[par][0]);
        unsigned long long aA0 = 0ull, aA1 = 0ull, aB0 = 0ull, aB1 = 0ull;
        #pragma unroll
        for (int k = 0; k < 8; k++) {
            unsigned long long h01, h23;
            unsigned ad = shb + ((unsigned)(lane + (k << 5)) << 4);   // float4-aligned
            asm volatile("ld.shared.v2.u64 {%0,%1}, [%2];"
                         : "=l"(h01), "=l"(h23) : "r"(ad));
            fma2(aA0, wA[2 * k], h01); fma2(aA1, wA[2 * k + 1], h23);
            fma2(aB0, wB[2 * k], h01); fma2(aB1, wB[2 * k + 1], h23);
        }
        float sa = sum2(aA0, aA1);
        float sb = sum2(aB0, aB1);
        #pragma unroll
        for (int o = 16; o; o >>= 1) {
            sa += __shfl_xor_sync(0xffffffffu, sa, o);
            sb += __shfl_xor_sync(0xffffffffu, sb, o);
        }

        // 4) lane 0: both tanhs, one 16B tagged publish FIRST, then out store
        if (lane == 0) {
            float hA = fast_tanh(sa + pa);
            float hB = fast_tanh(sb + pb);
            unsigned long long tg = (unsigned long long)(unsigned)(t + 2) << 32;
            st_cg_v2(g_H + (((t + 1) & 1) << 10) + rowA,
                     tg | (unsigned long long)__float_as_uint(hA),
                     tg | (unsigned long long)__float_as_uint(hB));
            reinterpret_cast<float2*>(out + (size_t)(t + 1) * HID)[rowA >> 1] =
                make_float2(hA, hB);
        }
        pa = pan; pb = pbn;
    }
}

// ---------------- launch ----------------
extern "C" void kernel_launch(void* const* d_in, const int* in_sizes, int n_in,
                              void* d_out, int out_size) {
    const int*   src  = (const int*)  d_in[0];  // [4096]
    const float* W    = (const float*)d_in[1];  // [32000,1024]
    const float* h0   = (const float*)d_in[2];  // [1024]
    const float* W_hi = (const float*)d_in[3];  // [1024,1024]
    const float* W_hh = (const float*)d_in[4];  // [1024,1024]
    const float* b    = (const float*)d_in[5];  // [1024]
    float* out = (float*)d_out;                 // [4097,1024]

    init_kernel<<<1, 1024>>>(h0, out);
    embed_kernel<<<SEQ, 256>>>(src, W);
    gemm_kernel<<<dim3(HID / BN, SEQ / BM), 256>>>(W_hi, b);
    rnn_kernel<<<NCTA, 512>>>(W_hh, out);
}

// round 11
// speedup vs baseline: 2.7962x; 1.0841x over previous
#include <cuda_runtime.h>
#include <cuda_fp16.h>

#define SEQ 4096
#define HID 1024
#define NCTA 32
#define EPSF 1e-12f

// Scratch (allocation-free rule: __device__ globals)
__device__ float g_Xn[SEQ * HID];              // normalized embeddings
__device__ float g_P[SEQ * HID];               // W_hi @ x_t + b, precomputed
// tagged h double buffer: one u64 per ROW-PAIR: hi32 = tag, lo32 = fp16x2 (rows 2s, 2s+1)
__device__ unsigned long long g_H16[2][HID / 2];

// ---------------- weak L2-cached ld/st (fast path) ----------------
__device__ __forceinline__ unsigned long long ld_cg(const unsigned long long* p) {
    unsigned long long v;
    asm volatile("ld.global.cg.u64 %0, [%1];" : "=l"(v) : "l"(p) : "memory");
    return v;
}
__device__ __forceinline__ void st_cg(unsigned long long* p, unsigned long long v) {
    asm volatile("st.global.cg.u64 [%0], %1;" :: "l"(p), "l"(v) : "memory");
}
// ---------------- strong relaxed load (progress-guarantee fallback only) ----------------
__device__ __forceinline__ unsigned long long ld_rlx(const unsigned long long* p) {
    unsigned long long v;
    asm volatile("ld.relaxed.gpu.global.u64 %0, [%1];" : "=l"(v) : "l"(p) : "memory");
    return v;
}

// ---------------- f32x2 packed helpers ----------------
__device__ __forceinline__ unsigned long long packff(float a, float b) {
    unsigned long long r;
    asm("mov.b64 %0, {%1,%2};" : "=l"(r) : "r"(__float_as_uint(a)), "r"(__float_as_uint(b)));
    return r;
}
__device__ __forceinline__ void fma2(unsigned long long& acc, unsigned long long w,
                                     unsigned long long h) {
    asm("fma.rn.f32x2 %0, %1, %2, %0;" : "+l"(acc) : "l"(w), "l"(h));
}
__device__ __forceinline__ float sum2(unsigned long long a, unsigned long long b) {
    unsigned long long s;
    asm("add.rn.f32x2 %0, %1, %2;" : "=l"(s) : "l"(a), "l"(b));
    unsigned lo, hi;
    asm("mov.b64 {%0,%1}, %2;" : "=r"(lo), "=r"(hi) : "l"(s));
    return __uint_as_float(lo) + __uint_as_float(hi);
}

// ---------------- fast tanh: 1 - 2/(e^{2x}+1) via ex2/rcp approx ----------------
__device__ __forceinline__ float fast_tanh(float x) {
    float e;
    asm("ex2.approx.f32 %0, %1;" : "=f"(e) : "f"(x * 2.8853900817779268f)); // 2*log2(e)
    float r;
    asm("rcp.approx.f32 %0, %1;" : "=f"(r) : "f"(e + 1.0f));
    return fmaf(-2.0f, r, 1.0f);
}

// ---------------- fp16x2 <-> float packing ----------------
__device__ __forceinline__ unsigned pack_h2(float a, float b) {
    __half2 h = __floats2half2_rn(a, b);
    return *reinterpret_cast<unsigned*>(&h);
}
__device__ __forceinline__ float2 unpack_h2(unsigned u) {
    __half2 h = *reinterpret_cast<__half2*>(&u);
    return __half22float2(h);
}

// ---------------- init: h0 -> out[0], tagged fp16 buf[0] (tag 1), clear buf[1] ----------------
__global__ __launch_bounds__(512) void init_kernel(const float* __restrict__ h0,
                                                   float* __restrict__ out) {
    int i = threadIdx.x;                        // 512 threads: one row-pair each
    float a = h0[2 * i], b = h0[2 * i + 1];
    out[2 * i] = a; out[2 * i + 1] = b;
    g_H16[0][i] = (1ull << 32) | (unsigned long long)pack_h2(a, b);
    g_H16[1][i] = 0ull;
}

// ---------------- embedding + L2 normalize ----------------
__global__ __launch_bounds__(256) void embed_kernel(const int* __restrict__ src,
                                                    const float* __restrict__ W) {
    const int t   = blockIdx.x;
    const int tid = threadIdx.x;
    const float4* row = reinterpret_cast<const float4*>(W) + (size_t)src[t] * (HID / 4);
    float4 v = row[tid];
    float s = v.x * v.x + v.y * v.y + v.z * v.z + v.w * v.w;
    #pragma unroll
    for (int o = 16; o; o >>= 1) s += __shfl_xor_sync(0xffffffffu, s, o);
    __shared__ float red[8];
    if ((tid & 31) == 0) red[tid >> 5] = s;
    __syncthreads();
    float tot = red[0] + red[1] + red[2] + red[3] + red[4] + red[5] + red[6] + red[7];
    float rn = 1.0f / fmaxf(sqrtf(tot), EPSF);
    float4 o4 = make_float4(v.x * rn, v.y * rn, v.z * rn, v.w * rn);
    reinterpret_cast<float4*>(g_Xn)[(size_t)t * (HID / 4) + tid] = o4;
}

// ---------------- GEMM: g_P[m][n] = sum_k g_Xn[m][k] * W_hi[n][k] + b[n] ----------------
#define BM 128
#define BN 64
#define BK 32
__global__ __launch_bounds__(256) void gemm_kernel(const float* __restrict__ Bw,
                                                   const float* __restrict__ bias) {
    __shared__ float As[BK][BM + 4];
    __shared__ float Bs[BK][BN + 4];
    const int tid = threadIdx.x;
    const int m0 = blockIdx.y * BM;
    const int n0 = blockIdx.x * BN;
    const int ty = tid >> 4;
    const int tx = tid & 15;

    float acc[8][4];
    #pragma unroll
    for (int i = 0; i < 8; i++)
        #pragma unroll
        for (int j = 0; j < 4; j++) acc[i][j] = 0.0f;

    for (int k0 = 0; k0 < HID; k0 += BK) {
        #pragma unroll
        for (int i = 0; i < 4; i++) {
            int idx = tid + i * 256;
            int r = idx >> 3;
            int kq = idx & 7;
            float4 f = reinterpret_cast<const float4*>(g_Xn)[(size_t)(m0 + r) * (HID / 4) + (k0 >> 2) + kq];
            As[kq * 4 + 0][r] = f.x;
            As[kq * 4 + 1][r] = f.y;
            As[kq * 4 + 2][r] = f.z;
            As[kq * 4 + 3][r] = f.w;
        }
        #pragma unroll
        for (int i = 0; i < 2; i++) {
            int idx = tid + i * 256;
            int r = idx >> 3;
            int kq = idx & 7;
            float4 f = reinterpret_cast<const float4*>(Bw)[(size_t)(n0 + r) * (HID / 4) + (k0 >> 2) + kq];
            Bs[kq * 4 + 0][r] = f.x;
            Bs[kq * 4 + 1][r] = f.y;
            Bs[kq * 4 + 2][r] = f.z;
            Bs[kq * 4 + 3][r] = f.w;
        }
        __syncthreads();
        #pragma unroll
        for (int k = 0; k < BK; k++) {
            float4 a0 = *reinterpret_cast<const float4*>(&As[k][ty * 8]);
            float4 a1 = *reinterpret_cast<const float4*>(&As[k][ty * 8 + 4]);
            float4 b0 = *reinterpret_cast<const float4*>(&Bs[k][tx * 4]);
            float ar[8] = {a0.x, a0.y, a0.z, a0.w, a1.x, a1.y, a1.z, a1.w};
            float br[4] = {b0.x, b0.y, b0.z, b0.w};
            #pragma unroll
            for (int i = 0; i < 8; i++)
                #pragma unroll
                for (int j = 0; j < 4; j++)
                    acc[i][j] = fmaf(ar[i], br[j], acc[i][j]);
        }
        __syncthreads();
    }

    float4 bb = reinterpret_cast<const float4*>(bias)[(n0 >> 2) + tx];
    #pragma unroll
    for (int i = 0; i < 8; i++) {
        int m = m0 + ty * 8 + i;
        float4 o = make_float4(acc[i][0] + bb.x, acc[i][1] + bb.y,
                               acc[i][2] + bb.z, acc[i][3] + bb.w);
        reinterpret_cast<float4*>(g_P)[(size_t)m * (HID / 4) + (n0 >> 2) + tx] = o;
    }
}

// ---------------- persistent RNN: fp16-packed tagged dataflow ----------------
// 32 CTAs x 16 warps (512 thr). Warp w of CTA c owns rows c*32+2w, c*32+2w+1.
// Sync channel: ONE u64 per row-pair = [tag32 | fp16x2], so each lane polls a
// single 8B .cg word (halved scan traffic vs fp32). Uniform non-divergent
// re-poll, strong relaxed fallback every 64 spins (progress guarantee). One
// __syncthreads per step; parity double-buffered smem (fp32 after convert);
// distance-2 overwrite induction unchanged. out[] keeps full fp32 values.
__global__ __launch_bounds__(512) void rnn_kernel(const float* __restrict__ Whh,
                                                  float* __restrict__ out) {
    __shared__ float4 shf[2][HID / 4];           // 8 KB, 16B-aligned staging
    const int tid  = threadIdx.x;
    const int warp = tid >> 5;
    const int lane = tid & 31;
    const int rowA = (blockIdx.x << 5) + (warp << 1);
    const int rowB = rowA + 1;
    const int myslot = (blockIdx.x << 4) + warp;   // publish slot = rowA/2

    // weights for both rows as packed f32x2 (16 u64 per row = 64 regs total)
    unsigned long long wA[16], wB[16];
    {
        const float4* wra = reinterpret_cast<const float4*>(Whh) + (size_t)rowA * (HID / 4);
        const float4* wrb = wra + (HID / 4);
        #pragma unroll
        for (int k = 0; k < 8; k++) {
            float4 a = wra[lane + (k << 5)];
            float4 b = wrb[lane + (k << 5)];
            wA[2 * k] = packff(a.x, a.y); wA[2 * k + 1] = packff(a.z, a.w);
            wB[2 * k] = packff(b.x, b.y); wB[2 * k + 1] = packff(b.z, b.w);
        }
    }

    float pa = g_P[rowA], pb = g_P[rowB];

    for (int t = 0; t < SEQ; ++t) {
        const unsigned tag = (unsigned)(t + 1);    // tag of h_t
        const int par = t & 1;

        // prefetch next-step P (independent of h)
        float pan = 0.f, pbn = 0.f;
        if (t + 1 < SEQ) {
            pan = g_P[(size_t)(t + 1) * HID + rowA];
            pbn = g_P[(size_t)(t + 1) * HID + rowB];
        }

        // 1) poll my single 8B tagged slot (slot index = tid)
        unsigned long long v;
        {
            const unsigned long long* gp = &g_H16[par][tid];
            int spins = 0;
            for (;;) {
                v = ld_cg(gp);
                if ((unsigned)(v >> 32) == tag) break;
                if ((++spins & 63) == 0) {         // rare strong fallback (progress)
                    v = ld_rlx(gp);
                    if ((unsigned)(v >> 32) == tag) break;
                }
            }
        }

        // 2) convert fp16x2 -> float2, stage to smem, then one CTA barrier
        reinterpret_cast<float2*>(&shf[par][0])[tid] = unpack_h2((unsigned)v);
        __syncthreads();

        // 3) dual-row dot product, packed f32x2 (8x LDS v2.u64 + 32 FFMA2)
        const unsigned shb = (unsigned)__cvta_generic_to_shared(&shf[par][0]);
        unsigned long long aA0 = 0ull, aA1 = 0ull, aB0 = 0ull, aB1 = 0ull;
        #pragma unroll
        for (int k = 0; k < 8; k++) {
            unsigned long long h01, h23;
            unsigned ad = shb + ((unsigned)(lane + (k << 5)) << 4);   // float4-aligned
            asm volatile("ld.shared.v2.u64 {%0,%1}, [%2];"
                         : "=l"(h01), "=l"(h23) : "r"(ad));
            fma2(aA0, wA[2 * k], h01); fma2(aA1, wA[2 * k + 1], h23);
            fma2(aB0, wB[2 * k], h01); fma2(aB1, wB[2 * k + 1], h23);
        }
        float sa = sum2(aA0, aA1);
        float sb = sum2(aB0, aB1);
        #pragma unroll
        for (int o = 16; o; o >>= 1) {
            sa += __shfl_xor_sync(0xffffffffu, sa, o);
            sb += __shfl_xor_sync(0xffffffffu, sb, o);
        }

        // 4) lane 0: both tanhs, one 8B tagged fp16 publish FIRST, then fp32 out
        if (lane == 0) {
            float hA = fast_tanh(sa + pa);
            float hB = fast_tanh(sb + pb);
            unsigned long long wv = ((unsigned long long)(unsigned)(t + 2) << 32)
                                  | (unsigned long long)pack_h2(hA, hB);
            st_cg(&g_H16[(t + 1) & 1][myslot], wv);
            reinterpret_cast<float2*>(out + (size_t)(t + 1) * HID)[myslot] =
                make_float2(hA, hB);
        }
        pa = pan; pb = pbn;
    }
}

// ---------------- launch ----------------
extern "C" void kernel_launch(void* const* d_in, const int* in_sizes, int n_in,
                              void* d_out, int out_size) {
    const int*   src  = (const int*)  d_in[0];  // [4096]
    const float* W    = (const float*)d_in[1];  // [32000,1024]
    const float* h0   = (const float*)d_in[2];  // [1024]
    const float* W_hi = (const float*)d_in[3];  // [1024,1024]
    const float* W_hh = (const float*)d_in[4];  // [1024,1024]
    const float* b    = (const float*)d_in[5];  // [1024]
    float* out = (float*)d_out;                 // [4097,1024]

    init_kernel<<<1, 512>>>(h0, out);
    embed_kernel<<<SEQ, 256>>>(src, W);
    gemm_kernel<<<dim3(HID / BN, SEQ / BM), 256>>>(W_hi, b);
    rnn_kernel<<<NCTA, 512>>>(W_hh, out);
}

// round 12
// speedup vs baseline: 3.2989x; 1.1798x over previous
#include <cuda_runtime.h>
#include <cuda_fp16.h>

#define SEQ 4096
#define HID 1024
#define NCTA 32
#define EPSF 1e-12f

// Scratch (allocation-free rule: __device__ globals)
__device__ float g_Xn[SEQ * HID];              // normalized embeddings
__device__ float g_P[SEQ * HID];               // W_hi @ x_t + b, precomputed
// tagged h double buffer: one u64 per ROW-PAIR: hi32 = tag, lo32 = fp16x2 (rows 2s, 2s+1)
__device__ unsigned long long g_H16[2][HID / 2];

// ---------------- weak L2-cached ld/st (fast path) ----------------
__device__ __forceinline__ void ld_cg_v2(const unsigned long long* p,
                                         unsigned long long& a, unsigned long long& b) {
    asm volatile("ld.global.cg.v2.u64 {%0,%1}, [%2];" : "=l"(a), "=l"(b) : "l"(p) : "memory");
}
__device__ __forceinline__ void st_cg(unsigned long long* p, unsigned long long v) {
    asm volatile("st.global.cg.u64 [%0], %1;" :: "l"(p), "l"(v) : "memory");
}
// ---------------- strong relaxed load (progress-guarantee fallback only) ----------------
__device__ __forceinline__ unsigned long long ld_rlx(const unsigned long long* p) {
    unsigned long long v;
    asm volatile("ld.relaxed.gpu.global.u64 %0, [%1];" : "=l"(v) : "l"(p) : "memory");
    return v;
}

// ---------------- f32x2 packed helpers ----------------
__device__ __forceinline__ unsigned long long packff(float a, float b) {
    unsigned long long r;
    asm("mov.b64 %0, {%1,%2};" : "=l"(r) : "r"(__float_as_uint(a)), "r"(__float_as_uint(b)));
    return r;
}
__device__ __forceinline__ void fma2(unsigned long long& acc, unsigned long long w,
                                     unsigned long long h) {
    asm("fma.rn.f32x2 %0, %1, %2, %0;" : "+l"(acc) : "l"(w), "l"(h));
}
__device__ __forceinline__ float sum2(unsigned long long a, unsigned long long b) {
    unsigned long long s;
    asm("add.rn.f32x2 %0, %1, %2;" : "=l"(s) : "l"(a), "l"(b));
    unsigned lo, hi;
    asm("mov.b64 {%0,%1}, %2;" : "=r"(lo), "=r"(hi) : "l"(s));
    return __uint_as_float(lo) + __uint_as_float(hi);
}

// ---------------- fast tanh: 1 - 2/(e^{2x}+1) via ex2/rcp approx ----------------
__device__ __forceinline__ float fast_tanh(float x) {
    float e;
    asm("ex2.approx.f32 %0, %1;" : "=f"(e) : "f"(x * 2.8853900817779268f)); // 2*log2(e)
    float r;
    asm("rcp.approx.f32 %0, %1;" : "=f"(r) : "f"(e + 1.0f));
    return fmaf(-2.0f, r, 1.0f);
}

// ---------------- fp16x2 <-> float packing ----------------
__device__ __forceinline__ unsigned pack_h2(float a, float b) {
    __half2 h = __floats2half2_rn(a, b);
    return *reinterpret_cast<unsigned*>(&h);
}
__device__ __forceinline__ float2 unpack_h2(unsigned u) {
    __half2 h = *reinterpret_cast<__half2*>(&u);
    return __half22float2(h);
}

// ---------------- init: h0 -> out[0], tagged fp16 buf[0] (tag 1), clear buf[1] ----------------
__global__ __launch_bounds__(512) void init_kernel(const float* __restrict__ h0,
                                                   float* __restrict__ out) {
    int i = threadIdx.x;                        // 512 threads: one row-pair each
    float a = h0[2 * i], b = h0[2 * i + 1];
    out[2 * i] = a; out[2 * i + 1] = b;
    g_H16[0][i] = (1ull << 32) | (unsigned long long)pack_h2(a, b);
    g_H16[1][i] = 0ull;
}

// ---------------- embedding + L2 normalize ----------------
__global__ __launch_bounds__(256) void embed_kernel(const int* __restrict__ src,
                                                    const float* __restrict__ W) {
    const int t   = blockIdx.x;
    const int tid = threadIdx.x;
    const float4* row = reinterpret_cast<const float4*>(W) + (size_t)src[t] * (HID / 4);
    float4 v = row[tid];
    float s = v.x * v.x + v.y * v.y + v.z * v.z + v.w * v.w;
    #pragma unroll
    for (int o = 16; o; o >>= 1) s += __shfl_xor_sync(0xffffffffu, s, o);
    __shared__ float red[8];
    if ((tid & 31) == 0) red[tid >> 5] = s;
    __syncthreads();
    float tot = red[0] + red[1] + red[2] + red[3] + red[4] + red[5] + red[6] + red[7];
    float rn = 1.0f / fmaxf(sqrtf(tot), EPSF);
    float4 o4 = make_float4(v.x * rn, v.y * rn, v.z * rn, v.w * rn);
    reinterpret_cast<float4*>(g_Xn)[(size_t)t * (HID / 4) + tid] = o4;
}

// ---------------- GEMM: g_P[m][n] = sum_k g_Xn[m][k] * W_hi[n][k] + b[n] ----------------
#define BM 128
#define BN 64
#define BK 32
__global__ __launch_bounds__(256) void gemm_kernel(const float* __restrict__ Bw,
                                                   const float* __restrict__ bias) {
    __shared__ float As[BK][BM + 4];
    __shared__ float Bs[BK][BN + 4];
    const int tid = threadIdx.x;
    const int m0 = blockIdx.y * BM;
    const int n0 = blockIdx.x * BN;
    const int ty = tid >> 4;
    const int tx = tid & 15;

    float acc[8][4];
    #pragma unroll
    for (int i = 0; i < 8; i++)
        #pragma unroll
        for (int j = 0; j < 4; j++) acc[i][j] = 0.0f;

    for (int k0 = 0; k0 < HID; k0 += BK) {
        #pragma unroll
        for (int i = 0; i < 4; i++) {
            int idx = tid + i * 256;
            int r = idx >> 3;
            int kq = idx & 7;
            float4 f = reinterpret_cast<const float4*>(g_Xn)[(size_t)(m0 + r) * (HID / 4) + (k0 >> 2) + kq];
            As[kq * 4 + 0][r] = f.x;
            As[kq * 4 + 1][r] = f.y;
            As[kq * 4 + 2][r] = f.z;
            As[kq * 4 + 3][r] = f.w;
        }
        #pragma unroll
        for (int i = 0; i < 2; i++) {
            int idx = tid + i * 256;
            int r = idx >> 3;
            int kq = idx & 7;
            float4 f = reinterpret_cast<const float4*>(Bw)[(size_t)(n0 + r) * (HID / 4) + (k0 >> 2) + kq];
            Bs[kq * 4 + 0][r] = f.x;
            Bs[kq * 4 + 1][r] = f.y;
            Bs[kq * 4 + 2][r] = f.z;
            Bs[kq * 4 + 3][r] = f.w;
        }
        __syncthreads();
        #pragma unroll
        for (int k = 0; k < BK; k++) {
            float4 a0 = *reinterpret_cast<const float4*>(&As[k][ty * 8]);
            float4 a1 = *reinterpret_cast<const float4*>(&As[k][ty * 8 + 4]);
            float4 b0 = *reinterpret_cast<const float4*>(&Bs[k][tx * 4]);
            float ar[8] = {a0.x, a0.y, a0.z, a0.w, a1.x, a1.y, a1.z, a1.w};
            float br[4] = {b0.x, b0.y, b0.z, b0.w};
            #pragma unroll
            for (int i = 0; i < 8; i++)
                #pragma unroll
                for (int j = 0; j < 4; j++)
                    acc[i][j] = fmaf(ar[i], br[j], acc[i][j]);
        }
        __syncthreads();
    }

    float4 bb = reinterpret_cast<const float4*>(bias)[(n0 >> 2) + tx];
    #pragma unroll
    for (int i = 0; i < 8; i++) {
        int m = m0 + ty * 8 + i;
        float4 o = make_float4(acc[i][0] + bb.x, acc[i][1] + bb.y,
                               acc[i][2] + bb.z, acc[i][3] + bb.w);
        reinterpret_cast<float4*>(g_P)[(size_t)m * (HID / 4) + (n0 >> 2) + tx] = o;
    }
}

// ---------------- persistent RNN: warp-specialized detection ----------------
// 32 CTAs x 16 warps (512 thr). Warp w of CTA c owns rows c*32+2w, c*32+2w+1.
// Sync channel: ONE u64 per row-pair = [tag32 | fp16x2] (8B-atomic, weak .cg).
// DETECTION IS SPECIALIZED: warp 0 of each CTA polls ALL 512 slots (16 per
// lane, 8x v2.u64, MLP=8), stages raw fp16x2 words into smem, then the
// per-step __syncthreads releases the 15 compute warps (parked in BAR, no
// issue pressure). 1K pollers chipwide instead of 16K -> poll storm cut 16x.
// Strong relaxed fallback every 64 poll sweeps (progress guarantee). Parity
// double-buffered smem; one bar/step (poller rewrites parity p only after the
// bar that proves all warps finished reading p); distance-2 overwrite
// induction unchanged. out[] keeps full fp32 values.
__global__ __launch_bounds__(512) void rnn_kernel(const float* __restrict__ Whh,
                                                  float* __restrict__ out) {
    __shared__ unsigned shq[2][HID / 2];         // 4 KB: [parity][fp16x2 per row-pair]
    const int tid  = threadIdx.x;
    const int warp = tid >> 5;
    const int lane = tid & 31;
    const int rowA = (blockIdx.x << 5) + (warp << 1);
    const int rowB = rowA + 1;
    const int myslot = (blockIdx.x << 4) + warp;   // publish slot = rowA/2

    // weights for both rows as packed f32x2 (16 u64 per row = 64 regs total)
    unsigned long long wA[16], wB[16];
    {
        const float4* wra = reinterpret_cast<const float4*>(Whh) + (size_t)rowA * (HID / 4);
        const float4* wrb = wra + (HID / 4);
        #pragma unroll
        for (int k = 0; k < 8; k++) {
            float4 a = wra[lane + (k << 5)];
            float4 b = wrb[lane + (k << 5)];
            wA[2 * k] = packff(a.x, a.y); wA[2 * k + 1] = packff(a.z, a.w);
            wB[2 * k] = packff(b.x, b.y); wB[2 * k + 1] = packff(b.z, b.w);
        }
    }

    const unsigned shb0 = (unsigned)__cvta_generic_to_shared(&shq[0][0]);
    float pa = g_P[rowA], pb = g_P[rowB];

    for (int t = 0; t < SEQ; ++t) {
        const unsigned tag = (unsigned)(t + 1);    // tag of h_t
        const int par = t & 1;

        // prefetch next-step P (independent of h)
        float pan = 0.f, pbn = 0.f;
        if (t + 1 < SEQ) {
            pan = g_P[(size_t)(t + 1) * HID + rowA];
            pbn = g_P[(size_t)(t + 1) * HID + rowB];
        }

        // 1) DETECTION (warp 0 only): poll all 512 slots, 16 per lane (8x v2)
        if (warp == 0) {
            const unsigned long long* base = &g_H16[par][0] + (lane << 1);
            unsigned long long s0[8], s1[8];
            int spins = 0;
            for (;;) {
                #pragma unroll
                for (int k = 0; k < 8; k++)
                    ld_cg_v2(base + (k << 6), s0[k], s1[k]);
                unsigned ok = 1u;
                #pragma unroll
                for (int k = 0; k < 8; k++)
                    ok &= (unsigned)((unsigned)(s0[k] >> 32) == tag) &
                          (unsigned)((unsigned)(s1[k] >> 32) == tag);
                if (ok) break;
                if ((++spins & 63) == 0) {         // rare strong fallback (progress)
                    unsigned ok2 = 1u;
                    #pragma unroll
                    for (int k = 0; k < 8; k++) {
                        s0[k] = ld_rlx(base + (k << 6));
                        s1[k] = ld_rlx(base + (k << 6) + 1);
                        ok2 &= (unsigned)((unsigned)(s0[k] >> 32) == tag) &
                               (unsigned)((unsigned)(s1[k] >> 32) == tag);
                    }
                    if (ok2) break;
                }
            }
            // stage raw fp16x2 words to smem (8x st.shared.v2.u32)
            const unsigned sb = shb0 + ((unsigned)par << 11) + ((unsigned)lane << 3);
            #pragma unroll
            for (int k = 0; k < 8; k++) {
                asm volatile("st.shared.v2.u32 [%0], {%1,%2};"
                             :: "r"(sb + ((unsigned)k << 8)),
                                "r"((unsigned)s0[k]), "r"((unsigned)s1[k]));
            }
        }
        __syncthreads();                           // releases 15 sleeping warps

        // 2) dual-row dot product: LDS.v2.u32 (fp16x2 pair) -> cvt -> FFMA2
        const unsigned hb = shb0 + ((unsigned)par << 11);
        unsigned long long aA0 = 0ull, aA1 = 0ull, aB0 = 0ull, aB1 = 0ull;
        #pragma unroll
        for (int k = 0; k < 8; k++) {
            unsigned w0, w1;
            asm volatile("ld.shared.v2.u32 {%0,%1}, [%2];"
                         : "=r"(w0), "=r"(w1)
                         : "r"(hb + ((unsigned)(lane + (k << 5)) << 3)));
            float2 f01 = unpack_h2(w0);
            float2 f23 = unpack_h2(w1);
            unsigned long long h01 = packff(f01.x, f01.y);
            unsigned long long h23 = packff(f23.x, f23.y);
            fma2(aA0, wA[2 * k], h01); fma2(aA1, wA[2 * k + 1], h23);
            fma2(aB0, wB[2 * k], h01); fma2(aB1, wB[2 * k + 1], h23);
        }
        float sa = sum2(aA0, aA1);
        float sb = sum2(aB0, aB1);
        #pragma unroll
        for (int o = 16; o; o >>= 1) {
            sa += __shfl_xor_sync(0xffffffffu, sa, o);
            sb += __shfl_xor_sync(0xffffffffu, sb, o);
        }

        // 3) lane 0: both tanhs, one 8B tagged fp16 publish FIRST, then fp32 out
        if (lane == 0) {
            float hA = fast_tanh(sa + pa);
            float hB = fast_tanh(sb + pb);
            unsigned long long wv = ((unsigned long long)(unsigned)(t + 2) << 32)
                                  | (unsigned long long)pack_h2(hA, hB);
            st_cg(&g_H16[(t + 1) & 1][myslot], wv);
            reinterpret_cast<float2*>(out + (size_t)(t + 1) * HID)[myslot] =
                make_float2(hA, hB);
        }
        pa = pan; pb = pbn;
    }
}

// ---------------- launch ----------------
extern "C" void kernel_launch(void* const* d_in, const int* in_sizes, int n_in,
                              void* d_out, int out_size) {
    const int*   src  = (const int*)  d_in[0];  // [4096]
    const float* W    = (const float*)d_in[1];  // [32000,1024]
    const float* h0   = (const float*)d_in[2];  // [1024]
    const float* W_hi = (const float*)d_in[3];  // [1024,1024]
    const float* W_hh = (const float*)d_in[4];  // [1024,1024]
    const float* b    = (const float*)d_in[5];  // [1024]
    float* out = (float*)d_out;                 // [4097,1024]

    init_kernel<<<1, 512>>>(h0, out);
    embed_kernel<<<SEQ, 256>>>(src, W);
    gemm_kernel<<<dim3(HID / BN, SEQ / BM), 256>>>(W_hi, b);
    rnn_kernel<<<NCTA, 512>>>(W_hh, out);
}